// round 5
// baseline (speedup 1.0000x reference)
#include <cuda_runtime.h>
#include <cstdint>

#define T_STEPS 300
#define E_DIM   300
#define H_DIM   512
#define G_DIM   2048   // 4*H
#define N_EXP   13
#define V_SIZE  400000
#define NCTA    128    // recurrent CTAs; 4 hidden units each
#define ROWS_PER_BLK 32
#define GATE_BLOCKS (N_EXP * (G_DIM / ROWS_PER_BLK))   // 832
#define SNAN_BITS 0x7fc00000

// Scratch (device globals: no allocation allowed)
__device__ float g_gates[T_STEPS * G_DIM];                      // input gates (+biases)
__device__ __align__(16) float g_h[(T_STEPS + 1) * H_DIM];      // step-indexed hidden states

// ---------------------------------------------------------------------------
// Volatile global access helpers (compiler cannot hoist/elide/fold these)
// ---------------------------------------------------------------------------
__device__ __forceinline__ float ld_vol_f(const float* p) {
    float v;
    asm volatile("ld.volatile.global.f32 %0, [%1];" : "=f"(v) : "l"(p));
    return v;
}
__device__ __forceinline__ float2 ld_vol_f2(const float2* p) {
    float2 v;
    asm volatile("ld.volatile.global.v2.f32 {%0,%1}, [%2];"
                 : "=f"(v.x), "=f"(v.y) : "l"(p));
    return v;
}
__device__ __forceinline__ void st_vol_f(float* p, float v) {
    asm volatile("st.volatile.global.f32 [%0], %1;" :: "l"(p), "f"(v));
}
__device__ __forceinline__ bool is_snan(float v) { return __float_as_int(v) == SNAN_BITS; }

// ---------------------------------------------------------------------------
// Kernel 1: re-init scratch each replay. g_h[0]=h0, rest sentinel; g_gates sentinel.
// ---------------------------------------------------------------------------
__global__ void init_kernel(const float* __restrict__ h0) {
    int idx = blockIdx.x * blockDim.x + threadIdx.x;
    const float sn = __int_as_float(SNAN_BITS);
    const int nh = (T_STEPS + 1) * H_DIM;
    if (idx < nh)                      g_h[idx] = (idx < H_DIM) ? h0[idx] : sn;
    else if (idx < nh + T_STEPS * G_DIM) g_gates[idx - nh] = sn;
}

// ---------------------------------------------------------------------------
// x-buffer probe: reference declares int64 but JAX w/o x64 yields int32.
// If truly int64, every odd 32-bit word is 0 (ids in [0, 4e5)).
// ---------------------------------------------------------------------------
__device__ __forceinline__ bool probe_is_i64(const int* __restrict__ x32) {
    bool all_zero = true;
    #pragma unroll
    for (int i = 1; i < 64; i += 2) all_zero &= (x32[i] == 0);
    return all_zero;
}
__device__ __forceinline__ int load_token(const int* __restrict__ x32, int t, bool i64) {
    int v = i64 ? x32[2 * t] : x32[t];
    return (v < 0) ? 0 : (v >= V_SIZE ? V_SIZE - 1 : v);
}

// ---------------------------------------------------------------------------
// Fused kernel. Blocks [0,128) = recurrent LSTM; blocks [128,960) = input gates.
// Shared pool is unioned between the two roles.
// ---------------------------------------------------------------------------
__global__ void __launch_bounds__(256) fused_kernel(
    const int* __restrict__ x32, const int* __restrict__ tags,
    const float* __restrict__ emb, const float* __restrict__ W_ih,
    const float* __restrict__ W_hh,
    const float* __restrict__ b_ih, const float* __restrict__ b_hh,
    const float* __restrict__ c0,
    const float* __restrict__ fc_w, const float* __restrict__ fc_b,
    float* __restrict__ d_out, int out_size)
{
    __shared__ __align__(16) float pool[ROWS_PER_BLK * E_DIM];  // 37.5 KB
    __shared__ float sx[E_DIM];
    __shared__ float sb[ROWS_PER_BLK];
    __shared__ int   stags[T_STEPS];
    __shared__ int   s_i64;

    const int tid = threadIdx.x;
    for (int i = tid; i < T_STEPS; i += 256) stags[i] = tags[i];

    if (blockIdx.x >= NCTA) {
        // ================= GATES ROLE =================
        const int gb    = blockIdx.x - NCTA;
        const int e     = gb / (G_DIM / ROWS_PER_BLK);
        const int chunk = gb % (G_DIM / ROWS_PER_BLK);
        const int row0  = chunk * ROWS_PER_BLK;

        float* sw = pool;
        const float* wsrc = W_ih + ((size_t)e * G_DIM + row0) * E_DIM;
        for (int i = tid; i < ROWS_PER_BLK * E_DIM; i += 256) sw[i] = wsrc[i];
        if (tid < ROWS_PER_BLK)
            sb[tid] = b_ih[e * G_DIM + row0 + tid] + b_hh[e * G_DIM + row0 + tid];
        if (tid == 0) s_i64 = probe_is_i64(x32) ? 1 : 0;
        __syncthreads();

        const bool i64  = (s_i64 != 0);
        const int row   = tid >> 3;   // 0..31
        const int lane8 = tid & 7;

        for (int t = 0; t < T_STEPS; t++) {
            if (stags[t] != e) continue;             // uniform branch (smem)
            const float* xe = emb + (size_t)load_token(x32, t, i64) * E_DIM;
            for (int i = tid; i < E_DIM; i += 256) sx[i] = xe[i];
            __syncthreads();
            float acc = 0.f;
            for (int k = lane8; k < E_DIM; k += 8)
                acc += sw[row * E_DIM + k] * sx[k];
            #pragma unroll
            for (int off = 4; off; off >>= 1)
                acc += __shfl_down_sync(0xffffffffu, acc, off, 8);
            if (lane8 == 0)
                st_vol_f(&g_gates[t * G_DIM + row0 + row], acc + sb[row]); // publish
            __syncthreads();
        }
        return;
    }

    // ================= LSTM ROLE =================
    float* sh   = pool;                          // 512 floats: h[s]
    float* ssum = pool + H_DIM;                  // 16: per-row dot sums
    float (*sgin)[16] = (float(*)[16])(pool + H_DIM + 16);  // double-buffered gates

    const int base   = blockIdx.x * 4;           // first hidden unit owned
    const int rid    = tid >> 4;                 // 0..15: gate row id
    const int lane16 = tid & 15;
    const int g      = rid >> 2;                 // gate: 0=i 1=f 2=g 3=o
    const int ul     = rid & 3;                  // unit within CTA
    const int row    = g * H_DIM + base + ul;    // global gate row

    float cval = 0.f, hval = 0.f;
    if (tid < 4) cval = c0[base + tid];
    __syncthreads();

    // Preload step-0 weights: thread handles k = lane16*4 + 64*m
    float4 wc[8], wn[8];
    {
        const float4* p = (const float4*)(W_hh + ((size_t)stags[0] * G_DIM + row) * H_DIM + lane16 * 4);
        #pragma unroll
        for (int m = 0; m < 8; m++) wc[m] = __ldg(&p[m * 16]);
    }

    const float2* ghp = (const float2*)g_h;

    for (int s = 0; s < T_STEPS; s++) {
        // 1. Prefetch next step's weights (tags known upfront -> hides L2 latency)
        {
            int sn = (s + 1 < T_STEPS) ? s + 1 : s;
            const float4* p = (const float4*)(W_hh + ((size_t)stags[sn] * G_DIM + row) * H_DIM + lane16 * 4);
            #pragma unroll
            for (int m = 0; m < 8; m++) wn[m] = __ldg(&p[m * 16]);
        }
        // 2. Prefetch this step's input gates (one value per lane for tid<16)
        float gin_pref = 0.f;
        const int gidx = s * G_DIM + (tid >> 2) * H_DIM + base + (tid & 3);
        if (tid < 16) gin_pref = __ldg(&g_gates[gidx]);

        // 3. Poll h[s]: each thread owns 2 floats; sentinel-bits = not ready
        float2 hv = ld_vol_f2(&ghp[s * (H_DIM / 2) + tid]);
        while (is_snan(hv.x) || is_snan(hv.y))
            hv = ld_vol_f2(&ghp[s * (H_DIM / 2) + tid]);
        sh[2 * tid]     = hv.x;
        sh[2 * tid + 1] = hv.y;
        if (tid < 16) {
            float gv_ = gin_pref;
            while (is_snan(gv_)) gv_ = ld_vol_f(&g_gates[gidx]);   // rare fallback
            sgin[s & 1][tid] = gv_;
        }
        __syncthreads();

        // 4. 16-lane dot product, 4 accumulators (short FMA chains)
        const float4* sh4 = (const float4*)sh;
        float a0 = 0.f, a1 = 0.f, a2 = 0.f, a3 = 0.f;
        #pragma unroll
        for (int m = 0; m < 8; m += 4) {
            float4 h0v = sh4[lane16 + (m + 0) * 16];
            float4 h1v = sh4[lane16 + (m + 1) * 16];
            float4 h2v = sh4[lane16 + (m + 2) * 16];
            float4 h3v = sh4[lane16 + (m + 3) * 16];
            a0 += wc[m+0].x * h0v.x + wc[m+0].y * h0v.y + wc[m+0].z * h0v.z + wc[m+0].w * h0v.w;
            a1 += wc[m+1].x * h1v.x + wc[m+1].y * h1v.y + wc[m+1].z * h1v.z + wc[m+1].w * h1v.w;
            a2 += wc[m+2].x * h2v.x + wc[m+2].y * h2v.y + wc[m+2].z * h2v.z + wc[m+2].w * h2v.w;
            a3 += wc[m+3].x * h3v.x + wc[m+3].y * h3v.y + wc[m+3].z * h3v.z + wc[m+3].w * h3v.w;
        }
        float acc = (a0 + a1) + (a2 + a3);
        #pragma unroll
        for (int off = 8; off; off >>= 1)
            acc += __shfl_down_sync(0xffffffffu, acc, off, 16);
        if (lane16 == 0) ssum[rid] = acc;
        __syncthreads();

        // 5. Parallel nonlinearity in warp 0 lanes 0-15 (one MUFU path each),
        //    gather i/f/g/o to lanes 0-3, update c/h, publish h[s+1].
        if (tid < 16) {
            float v = sgin[s & 1][tid] + ssum[tid];
            bool isg = ((tid >> 2) == 2);                 // tanh gate
            float e  = __expf(isg ? -2.f * v : -v);
            float val = __fdividef(isg ? 1.f - e : 1.f, 1.f + e);  // tanh or sigmoid
            int u = tid & 3;
            float fv = __shfl_sync(0xffffu, val, u + 4);
            float gv = __shfl_sync(0xffffu, val, u + 8);
            float ov = __shfl_sync(0xffffu, val, u + 12);
            if (tid < 4) {
                cval = fv * cval + val * gv;              // val = i for lanes 0-3
                float e2 = __expf(-2.f * cval);
                hval = ov * __fdividef(1.f - e2, 1.f + e2);
                st_vol_f(&g_h[(s + 1) * H_DIM + base + tid], hval);   // the "flag"
            }
        }
        #pragma unroll
        for (int m = 0; m < 8; m++) wc[m] = wn[m];
    }

    // Output layout: [out(1), h(512), c(512)] — h/c only if harness sized it so
    if (tid < 4 && out_size >= 1 + 2 * H_DIM) {
        d_out[1 + base + tid]         = hval;
        d_out[1 + H_DIM + base + tid] = cval;
    }

    // Block 0 computes out = sigmoid(h_T . fc_w + fc_b)  (fused out_kernel)
    if (blockIdx.x == 0) {
        const float2* hp = (const float2*)(g_h + T_STEPS * H_DIM);
        float2 hv = ld_vol_f2(&hp[tid]);
        while (is_snan(hv.x) || is_snan(hv.y)) hv = ld_vol_f2(&hp[tid]);
        float v = hv.x * __ldg(&fc_w[2 * tid]) + hv.y * __ldg(&fc_w[2 * tid + 1]);
        #pragma unroll
        for (int off = 16; off; off >>= 1) v += __shfl_down_sync(0xffffffffu, v, off);
        if ((tid & 31) == 0) ssum[tid >> 5] = v;   // reuse ssum smem (8 slots)
        __syncthreads();
        if (tid < 8) {
            v = ssum[tid];
            #pragma unroll
            for (int off = 4; off; off >>= 1) v += __shfl_down_sync(0xffu, v, off, 8);
            if (tid == 0) d_out[0] = __fdividef(1.f, 1.f + __expf(-(v + fc_b[0])));
        }
    }
}

// ---------------------------------------------------------------------------
// Launch. Input order: x, tags, h0, c0, emb, W_ih, W_hh, b_ih, b_hh, fc_w, fc_b.
// ---------------------------------------------------------------------------
extern "C" void kernel_launch(void* const* d_in, const int* in_sizes, int n_in,
                              void* d_out, int out_size)
{
    const int*   x32  = (const int*)  d_in[0];   // int32 OR int64 (device probe)
    const int*   tags = (const int*)  d_in[1];
    const float* h0   = (const float*)d_in[2];
    const float* c0   = (const float*)d_in[3];
    const float* emb  = (const float*)d_in[4];
    const float* W_ih = (const float*)d_in[5];
    const float* W_hh = (const float*)d_in[6];
    const float* b_ih = (const float*)d_in[7];
    const float* b_hh = (const float*)d_in[8];
    const float* fc_w = (const float*)d_in[9];
    const float* fc_b = (const float*)d_in[10];
    float* out = (float*)d_out;

    const int n_init = (T_STEPS + 1) * H_DIM + T_STEPS * G_DIM;
    init_kernel<<<(n_init + 511) / 512, 512>>>(h0);
    fused_kernel<<<NCTA + GATE_BLOCKS, 256>>>(x32, tags, emb, W_ih, W_hh,
                                              b_ih, b_hh, c0, fc_w, fc_b,
                                              out, out_size);
}